// round 3
// baseline (speedup 1.0000x reference)
#include <cuda_runtime.h>

// Biquad DF2T over time axis, B=512 channels, T=48000 samples, fp32.
//
// Parallel-in-time via exact affine chunked scan:
//   state z = (z1, z2),  z[n+1] = A z[n] + v x[n],  A = [[-a1, 1], [-a2, 0]]
//   Pass 1: per (channel, chunk) run recurrence from z=0 -> offset w[b][k]
//   Combine: per channel, z_start[k+1] = A^C z_start[k] + w[k]  (A^C in fp64)
//   Pass 3: per (channel, chunk) run recurrence from z_start, write y
//
// Tiled through shared memory (32 channels x 32 time steps, pad-33 rows) so
// all global traffic is coalesced float4. Total HBM traffic ~282 MB.

#define B_CH   512
#define T_LEN  48000
#define C_LEN  192          // chunk length (multiple of 32)
#define K_CHK  250          // T_LEN / C_LEN
#define NTILE  6            // C_LEN / 32
#define WPB    8            // warps per block
#define NGRP   16           // channel groups of 32 (B_CH / 32)
#define NBLK   ((NGRP * K_CHK) / WPB)   // 500 blocks

// Scratch: per-(chunk, channel) zero-init chunk-end state and chunk-start state.
// Laid out [k][b] so lane stores/loads are coalesced.
__device__ float g_wz1[K_CHK * B_CH];
__device__ float g_wz2[K_CHK * B_CH];
__device__ float g_zs1[K_CHK * B_CH];
__device__ float g_zs2[K_CHK * B_CH];

template <bool WRITE_Y>
__global__ __launch_bounds__(WPB * 32) void biquad_pass(
    const float* __restrict__ x,
    const float* __restrict__ b0p, const float* __restrict__ b1p,
    const float* __restrict__ b2p, const float* __restrict__ a1p,
    const float* __restrict__ a2p, float* __restrict__ out)
{
    __shared__ float tile[WPB][32][33];   // pad 33: conflict-free row access

    const int w    = threadIdx.x >> 5;
    const int lane = threadIdx.x & 31;
    const int wg   = blockIdx.x * WPB + w;      // 0 .. NGRP*K_CHK-1
    const int cg   = wg & (NGRP - 1);           // channel group
    const int k    = wg >> 4;                   // chunk index
    const int ch   = cg * 32 + lane;            // this lane's channel

    const float b0 = b0p[ch], b1 = b1p[ch], b2 = b2p[ch];
    const float a1 = a1p[ch], a2 = a2p[ch];

    float z1, z2;
    if (WRITE_Y) {
        z1 = g_zs1[k * B_CH + ch];
        z2 = g_zs2[k * B_CH + ch];
    } else {
        z1 = 0.0f; z2 = 0.0f;
    }

    const int t0 = k * C_LEN;
    const int lr = lane >> 3;          // 0..3  (row within 4-row group)
    const int lc = (lane & 7) * 4;     // 0,4,...,28 (col of float4)

    #pragma unroll 1
    for (int s = 0; s < NTILE; s++) {
        const int ts = t0 + s * 32;

        // Cooperative coalesced load: 32 channels x 32 time steps.
        #pragma unroll
        for (int i = 0; i < 8; i++) {
            const int r = i * 4 + lr;
            float4 v = *reinterpret_cast<const float4*>(
                x + (size_t)(cg * 32 + r) * T_LEN + ts + lc);
            tile[w][r][lc + 0] = v.x;
            tile[w][r][lc + 1] = v.y;
            tile[w][r][lc + 2] = v.z;
            tile[w][r][lc + 3] = v.w;
        }
        __syncwarp();

        // Each lane owns one channel row: serial DF2T over 32 samples.
        #pragma unroll
        for (int j = 0; j < 32; j++) {
            const float xv = tile[w][lane][j];
            const float y  = fmaf(b0, xv, z1);
            const float t  = fmaf(b1, xv, z2);
            z1 = fmaf(-a1, y, t);
            z2 = fmaf(-a2, y, b2 * xv);
            if (WRITE_Y) tile[w][lane][j] = y;   // same-lane slot: no hazard
        }
        __syncwarp();

        if (WRITE_Y) {
            // Cooperative coalesced store of the y tile.
            #pragma unroll
            for (int i = 0; i < 8; i++) {
                const int r = i * 4 + lr;
                float4 v;
                v.x = tile[w][r][lc + 0];
                v.y = tile[w][r][lc + 1];
                v.z = tile[w][r][lc + 2];
                v.w = tile[w][r][lc + 3];
                *reinterpret_cast<float4*>(
                    out + (size_t)(cg * 32 + r) * T_LEN + ts + lc) = v;
            }
            __syncwarp();
        }
    }

    if (!WRITE_Y) {
        g_wz1[k * B_CH + ch] = z1;
        g_wz2[k * B_CH + ch] = z2;
    }
}

#define CB 10   // combine batch size (K_CHK = 250 = 25 batches of 10)

__global__ void biquad_combine(const float* __restrict__ a1p,
                               const float* __restrict__ a2p)
{
    const int b = blockIdx.x * blockDim.x + threadIdx.x;
    if (b >= B_CH) return;

    const double a1 = (double)a1p[b];
    const double a2 = (double)a2p[b];

    // A = [[-a1, 1], [-a2, 0]]; compute A^C_LEN by repeated squaring (fp64).
    double r00 = 1.0, r01 = 0.0, r10 = 0.0, r11 = 1.0;
    double p00 = -a1, p01 = 1.0, p10 = -a2, p11 = 0.0;
    int e = C_LEN;
    while (e) {
        if (e & 1) {
            const double n00 = r00 * p00 + r01 * p10;
            const double n01 = r00 * p01 + r01 * p11;
            const double n10 = r10 * p00 + r11 * p10;
            const double n11 = r10 * p01 + r11 * p11;
            r00 = n00; r01 = n01; r10 = n10; r11 = n11;
        }
        e >>= 1;
        if (e) {
            const double q00 = p00 * p00 + p01 * p10;
            const double q01 = p00 * p01 + p01 * p11;
            const double q10 = p10 * p00 + p11 * p10;
            const double q11 = p10 * p01 + p11 * p11;
            p00 = q00; p01 = q01; p10 = q10; p11 = q11;
        }
    }
    const float m00 = (float)r00, m01 = (float)r01;
    const float m10 = (float)r10, m11 = (float)r11;

    // Sequential combine over chunks. Batched: issue 2*CB independent loads
    // up front (MLP), then run the CB dependent FMA steps, then store the
    // z_start values. Amortizes the L2 latency across the batch.
    float z1 = 0.0f, z2 = 0.0f;
    #pragma unroll 1
    for (int kb = 0; kb < K_CHK; kb += CB) {
        float w1[CB], w2[CB];
        #pragma unroll
        for (int i = 0; i < CB; i++) {
            w1[i] = g_wz1[(kb + i) * B_CH + b];
            w2[i] = g_wz2[(kb + i) * B_CH + b];
        }
        float s1[CB], s2[CB];
        #pragma unroll
        for (int i = 0; i < CB; i++) {
            s1[i] = z1;
            s2[i] = z2;
            const float n1 = fmaf(m00, z1, fmaf(m01, z2, w1[i]));
            const float n2 = fmaf(m10, z1, fmaf(m11, z2, w2[i]));
            z1 = n1; z2 = n2;
        }
        #pragma unroll
        for (int i = 0; i < CB; i++) {
            g_zs1[(kb + i) * B_CH + b] = s1[i];
            g_zs2[(kb + i) * B_CH + b] = s2[i];
        }
    }
}

extern "C" void kernel_launch(void* const* d_in, const int* in_sizes, int n_in,
                              void* d_out, int out_size)
{
    const float* x  = (const float*)d_in[0];
    const float* b0 = (const float*)d_in[1];
    const float* b1 = (const float*)d_in[2];
    const float* b2 = (const float*)d_in[3];
    const float* a1 = (const float*)d_in[4];
    const float* a2 = (const float*)d_in[5];
    float* out = (float*)d_out;

    biquad_pass<false><<<NBLK, WPB * 32>>>(x, b0, b1, b2, a1, a2, nullptr);
    biquad_combine<<<16, 32>>>(a1, a2);
    biquad_pass<true><<<NBLK, WPB * 32>>>(x, b0, b1, b2, a1, a2, out);
}

// round 5
// speedup vs baseline: 1.1223x; 1.1223x over previous
#include <cuda_runtime.h>

// Biquad DF2T, B=512 channels, T=48000, fp32 — exact affine chunked scan.
//   Pass 1: per (channel, chunk) recurrence from z=0 -> offset w[b][k]
//   Combine: z_start[k+1] = A^C z_start[k] + w[k]  (A^C via fp64 pow)
//   Pass 3: recurrence from z_start, write y.
//
// Loads: each lane reads its own channel row directly as float4 (first LDG of
// a 32-sample group misses, next 7 hit L1) with a 2-group register pipeline so
// ~8 loads stay in flight per warp. Stores (pass 3 only) are staged through a
// pad-33 smem tile and written as coalesced float4.

#define B_CH   512
#define T_LEN  48000
#define C_LEN  192          // chunk length
#define K_CHK  250          // T_LEN / C_LEN
#define NGR    6            // 32-sample groups per chunk
#define WPB    4            // warps per block
#define NGRP   16           // channel groups of 32
#define NBLK   ((NGRP * K_CHK) / WPB)   // 1000 blocks

__device__ float g_wz1[K_CHK * B_CH];
__device__ float g_wz2[K_CHK * B_CH];
__device__ float g_zs1[K_CHK * B_CH];
__device__ float g_zs2[K_CHK * B_CH];

template <bool WRITE_Y>
__global__ __launch_bounds__(WPB * 32) void biquad_pass(
    const float* __restrict__ x,
    const float* __restrict__ b0p, const float* __restrict__ b1p,
    const float* __restrict__ b2p, const float* __restrict__ a1p,
    const float* __restrict__ a2p, float* __restrict__ out)
{
    __shared__ float ytile[WRITE_Y ? WPB * 32 * 33 : WPB];

    const int w    = threadIdx.x >> 5;
    const int lane = threadIdx.x & 31;
    const int wg   = blockIdx.x * WPB + w;      // 0 .. NGRP*K_CHK-1
    const int cg   = wg & (NGRP - 1);           // channel group
    const int k    = wg >> 4;                   // chunk index
    const int ch   = cg * 32 + lane;

    const float b0  = b0p[ch], b1 = b1p[ch], b2 = b2p[ch];
    const float na1 = -a1p[ch], na2 = -a2p[ch];

    float z1, z2;
    if (WRITE_Y) {
        z1 = g_zs1[k * B_CH + ch];
        z2 = g_zs2[k * B_CH + ch];
    } else {
        z1 = 0.0f; z2 = 0.0f;
    }

    const float4* __restrict__ xp = reinterpret_cast<const float4*>(
        x + (size_t)ch * T_LEN + k * C_LEN);

    float* yrow = &ytile[WRITE_Y ? (w * 32 + lane) * 33 : 0];

    // One 32-sample group: consume 8 float4 from regs, run the DF2T chain.
    auto do_group = [&](const float4* xg, int g) {
        #pragma unroll
        for (int i = 0; i < 8; i++) {
            const float4 v = xg[i];
            #pragma unroll
            for (int d = 0; d < 4; d++) {
                const float xv = (d == 0) ? v.x : (d == 1) ? v.y
                               : (d == 2) ? v.z : v.w;
                const float y = fmaf(b0, xv, z1);
                const float t = fmaf(b1, xv, z2);
                z1 = fmaf(na1, y, t);
                z2 = fmaf(na2, y, b2 * xv);
                if (WRITE_Y) yrow[i * 4 + d] = y;
            }
        }
        if (WRITE_Y) {
            __syncwarp();
            const int lr = lane >> 3;          // 0..3
            const int lc = (lane & 7) * 4;     // 0..28
            const int ts = k * C_LEN + g * 32;
            #pragma unroll
            for (int i = 0; i < 8; i++) {
                const int r = i * 4 + lr;
                const float* src = &ytile[(w * 32 + r) * 33 + lc];
                float4 vv;
                vv.x = src[0]; vv.y = src[1]; vv.z = src[2]; vv.w = src[3];
                *reinterpret_cast<float4*>(
                    out + (size_t)(cg * 32 + r) * T_LEN + ts + lc) = vv;
            }
            __syncwarp();
        }
    };

    // 2-group register pipeline over NGR=6 groups (3 pairs).
    float4 xa[8], xb[8];
    #pragma unroll
    for (int i = 0; i < 8; i++) xa[i] = xp[i];

    #pragma unroll 1
    for (int p = 0; p < NGR / 2; p++) {
        #pragma unroll
        for (int i = 0; i < 8; i++) xb[i] = xp[(2 * p + 1) * 8 + i];
        do_group(xa, 2 * p);
        if (p < NGR / 2 - 1) {
            #pragma unroll
            for (int i = 0; i < 8; i++) xa[i] = xp[(2 * p + 2) * 8 + i];
        }
        do_group(xb, 2 * p + 1);
    }

    if (!WRITE_Y) {
        g_wz1[k * B_CH + ch] = z1;
        g_wz2[k * B_CH + ch] = z2;
    }
}

#define CB 10   // combine batch size (250 = 25 batches of 10)

__global__ void biquad_combine(const float* __restrict__ a1p,
                               const float* __restrict__ a2p)
{
    const int b = blockIdx.x * blockDim.x + threadIdx.x;
    if (b >= B_CH) return;

    const double a1 = (double)a1p[b];
    const double a2 = (double)a2p[b];

    // A = [[-a1, 1], [-a2, 0]]; A^C_LEN by repeated squaring in fp64.
    double r00 = 1.0, r01 = 0.0, r10 = 0.0, r11 = 1.0;
    double p00 = -a1, p01 = 1.0, p10 = -a2, p11 = 0.0;
    int e = C_LEN;
    while (e) {
        if (e & 1) {
            const double n00 = r00 * p00 + r01 * p10;
            const double n01 = r00 * p01 + r01 * p11;
            const double n10 = r10 * p00 + r11 * p10;
            const double n11 = r10 * p01 + r11 * p11;
            r00 = n00; r01 = n01; r10 = n10; r11 = n11;
        }
        e >>= 1;
        if (e) {
            const double q00 = p00 * p00 + p01 * p10;
            const double q01 = p00 * p01 + p01 * p11;
            const double q10 = p10 * p00 + p11 * p10;
            const double q11 = p10 * p01 + p11 * p11;
            p00 = q00; p01 = q01; p10 = q10; p11 = q11;
        }
    }
    const float m00 = (float)r00, m01 = (float)r01;
    const float m10 = (float)r10, m11 = (float)r11;

    // Batched sequential combine: 2*CB independent loads up front (MLP),
    // then CB dependent FMA steps, then store z_start values.
    float z1 = 0.0f, z2 = 0.0f;
    #pragma unroll 1
    for (int kb = 0; kb < K_CHK; kb += CB) {
        float w1[CB], w2[CB];
        #pragma unroll
        for (int i = 0; i < CB; i++) {
            w1[i] = g_wz1[(kb + i) * B_CH + b];
            w2[i] = g_wz2[(kb + i) * B_CH + b];
        }
        float s1[CB], s2[CB];
        #pragma unroll
        for (int i = 0; i < CB; i++) {
            s1[i] = z1;
            s2[i] = z2;
            const float n1 = fmaf(m00, z1, fmaf(m01, z2, w1[i]));
            const float n2 = fmaf(m10, z1, fmaf(m11, z2, w2[i]));
            z1 = n1; z2 = n2;
        }
        #pragma unroll
        for (int i = 0; i < CB; i++) {
            g_zs1[(kb + i) * B_CH + b] = s1[i];
            g_zs2[(kb + i) * B_CH + b] = s2[i];
        }
    }
}

extern "C" void kernel_launch(void* const* d_in, const int* in_sizes, int n_in,
                              void* d_out, int out_size)
{
    const float* x  = (const float*)d_in[0];
    const float* b0 = (const float*)d_in[1];
    const float* b1 = (const float*)d_in[2];
    const float* b2 = (const float*)d_in[3];
    const float* a1 = (const float*)d_in[4];
    const float* a2 = (const float*)d_in[5];
    float* out = (float*)d_out;

    biquad_pass<false><<<NBLK, WPB * 32>>>(x, b0, b1, b2, a1, a2, nullptr);
    biquad_combine<<<16, 32>>>(a1, a2);
    biquad_pass<true><<<NBLK, WPB * 32>>>(x, b0, b1, b2, a1, a2, out);
}

// round 6
// speedup vs baseline: 1.3446x; 1.1981x over previous
#include <cuda_runtime.h>

// Biquad DF2T, B=512 channels, T=48000, fp32 — exact affine chunked scan.
//   Pass 1: per (channel, chunk) recurrence from z=0 -> offset w[b][k]
//   Combine: z_start[k+1] = A^C z_start[k] + w[k]  (A^C via fp64 pow)
//   Pass 3: recurrence from z_start, write y.
//
// All global traffic is coalesced float4 (4 lines per LDG). x tiles are
// register-pipelined: group g+1's LDGs are issued before group g's FMA chain,
// so loads stay in flight during compute. Smem (pad-33 rows) is used only to
// transpose between the coalesced I/O layout and the lane-owns-a-channel
// compute layout; all smem access patterns are bank-conflict-free.

#define B_CH   512
#define T_LEN  48000
#define C_LEN  192          // chunk length
#define K_CHK  250          // T_LEN / C_LEN
#define NGR    6            // 32-sample groups per chunk
#define WPB    4            // warps per block
#define NGRP   16           // channel groups of 32
#define NBLK   ((NGRP * K_CHK) / WPB)   // 1000 blocks

__device__ float g_wz1[K_CHK * B_CH];
__device__ float g_wz2[K_CHK * B_CH];
__device__ float g_zs1[K_CHK * B_CH];
__device__ float g_zs2[K_CHK * B_CH];

template <bool WRITE_Y>
__global__ __launch_bounds__(WPB * 32) void biquad_pass(
    const float* __restrict__ x,
    const float* __restrict__ b0p, const float* __restrict__ b1p,
    const float* __restrict__ b2p, const float* __restrict__ a1p,
    const float* __restrict__ a2p, float* __restrict__ out)
{
    __shared__ float tile[WPB][32][33];   // pad-33: conflict-free everywhere

    const int w    = threadIdx.x >> 5;
    const int lane = threadIdx.x & 31;
    const int wg   = blockIdx.x * WPB + w;      // 0 .. NGRP*K_CHK-1
    const int cg   = wg & (NGRP - 1);           // channel group
    const int k    = wg >> 4;                   // chunk index
    const int ch   = cg * 32 + lane;

    const float b0  = b0p[ch], b1 = b1p[ch], b2 = b2p[ch];
    const float na1 = -a1p[ch], na2 = -a2p[ch];

    float z1, z2;
    if (WRITE_Y) {
        z1 = g_zs1[k * B_CH + ch];
        z2 = g_zs2[k * B_CH + ch];
    } else {
        z1 = 0.0f; z2 = 0.0f;
    }

    const int lr  = lane >> 3;          // 0..3   (row within 4-row slab)
    const int lc  = (lane & 7) * 4;     // 0..28  (float4 column)
    const float* __restrict__ xbase = x + (size_t)(cg * 32) * T_LEN + k * C_LEN;
    float* __restrict__ obase = WRITE_Y
        ? out + (size_t)(cg * 32) * T_LEN + k * C_LEN : nullptr;

    // Prologue: coalesced load of group 0 into registers (4 lines / LDG).
    float4 r[8];
    #pragma unroll
    for (int i = 0; i < 8; i++)
        r[i] = *reinterpret_cast<const float4*>(
            xbase + (size_t)(i * 4 + lr) * T_LEN + lc);

    #pragma unroll 1
    for (int g = 0; g < NGR; g++) {
        // Scatter the register tile into smem (conflict-free: bank =
        // (4i + lr + lc + d) mod 32 is a lane permutation per (i, d)).
        #pragma unroll
        for (int i = 0; i < 8; i++) {
            const int rr = i * 4 + lr;
            tile[w][rr][lc + 0] = r[i].x;
            tile[w][rr][lc + 1] = r[i].y;
            tile[w][rr][lc + 2] = r[i].z;
            tile[w][rr][lc + 3] = r[i].w;
        }
        __syncwarp();

        // Prefetch next group NOW — these LDGs ride out the FMA chain.
        if (g + 1 < NGR) {
            #pragma unroll
            for (int i = 0; i < 8; i++)
                r[i] = *reinterpret_cast<const float4*>(
                    xbase + (size_t)(i * 4 + lr) * T_LEN + (g + 1) * 32 + lc);
        }

        // Serial DF2T over this lane's channel row (bank = (lane+j) mod 32).
        #pragma unroll
        for (int j = 0; j < 32; j++) {
            const float xv = tile[w][lane][j];
            const float y  = fmaf(b0, xv, z1);
            const float t  = fmaf(b1, xv, z2);
            z1 = fmaf(na1, y, t);
            z2 = fmaf(na2, y, b2 * xv);
            if (WRITE_Y) tile[w][lane][j] = y;   // own row: no hazard
        }
        __syncwarp();

        if (WRITE_Y) {
            // Coalesced gather-store of the y tile.
            #pragma unroll
            for (int i = 0; i < 8; i++) {
                const int rr = i * 4 + lr;
                const float* src = &tile[w][rr][lc];
                float4 vv;
                vv.x = src[0]; vv.y = src[1]; vv.z = src[2]; vv.w = src[3];
                *reinterpret_cast<float4*>(
                    obase + (size_t)rr * T_LEN + g * 32 + lc) = vv;
            }
            __syncwarp();
        }
    }

    if (!WRITE_Y) {
        g_wz1[k * B_CH + ch] = z1;
        g_wz2[k * B_CH + ch] = z2;
    }
}

#define CB 10   // combine batch size (250 = 25 batches of 10)

__global__ void biquad_combine(const float* __restrict__ a1p,
                               const float* __restrict__ a2p)
{
    const int b = blockIdx.x * blockDim.x + threadIdx.x;
    if (b >= B_CH) return;

    const double a1 = (double)a1p[b];
    const double a2 = (double)a2p[b];

    // A = [[-a1, 1], [-a2, 0]]; A^C_LEN by repeated squaring in fp64.
    double r00 = 1.0, r01 = 0.0, r10 = 0.0, r11 = 1.0;
    double p00 = -a1, p01 = 1.0, p10 = -a2, p11 = 0.0;
    int e = C_LEN;
    while (e) {
        if (e & 1) {
            const double n00 = r00 * p00 + r01 * p10;
            const double n01 = r00 * p01 + r01 * p11;
            const double n10 = r10 * p00 + r11 * p10;
            const double n11 = r10 * p01 + r11 * p11;
            r00 = n00; r01 = n01; r10 = n10; r11 = n11;
        }
        e >>= 1;
        if (e) {
            const double q00 = p00 * p00 + p01 * p10;
            const double q01 = p00 * p01 + p01 * p11;
            const double q10 = p10 * p00 + p11 * p10;
            const double q11 = p10 * p01 + p11 * p11;
            p00 = q00; p01 = q01; p10 = q10; p11 = q11;
        }
    }
    const float m00 = (float)r00, m01 = (float)r01;
    const float m10 = (float)r10, m11 = (float)r11;

    // Batched sequential combine: 2*CB independent loads up front (MLP),
    // then CB dependent FMA steps, then store z_start values.
    float z1 = 0.0f, z2 = 0.0f;
    #pragma unroll 1
    for (int kb = 0; kb < K_CHK; kb += CB) {
        float w1[CB], w2[CB];
        #pragma unroll
        for (int i = 0; i < CB; i++) {
            w1[i] = g_wz1[(kb + i) * B_CH + b];
            w2[i] = g_wz2[(kb + i) * B_CH + b];
        }
        float s1[CB], s2[CB];
        #pragma unroll
        for (int i = 0; i < CB; i++) {
            s1[i] = z1;
            s2[i] = z2;
            const float n1 = fmaf(m00, z1, fmaf(m01, z2, w1[i]));
            const float n2 = fmaf(m10, z1, fmaf(m11, z2, w2[i]));
            z1 = n1; z2 = n2;
        }
        #pragma unroll
        for (int i = 0; i < CB; i++) {
            g_zs1[(kb + i) * B_CH + b] = s1[i];
            g_zs2[(kb + i) * B_CH + b] = s2[i];
        }
    }
}

extern "C" void kernel_launch(void* const* d_in, const int* in_sizes, int n_in,
                              void* d_out, int out_size)
{
    const float* x  = (const float*)d_in[0];
    const float* b0 = (const float*)d_in[1];
    const float* b1 = (const float*)d_in[2];
    const float* b2 = (const float*)d_in[3];
    const float* a1 = (const float*)d_in[4];
    const float* a2 = (const float*)d_in[5];
    float* out = (float*)d_out;

    biquad_pass<false><<<NBLK, WPB * 32>>>(x, b0, b1, b2, a1, a2, nullptr);
    biquad_combine<<<16, 32>>>(a1, a2);
    biquad_pass<true><<<NBLK, WPB * 32>>>(x, b0, b1, b2, a1, a2, out);
}

// round 7
// speedup vs baseline: 1.5737x; 1.1704x over previous
#include <cuda_runtime.h>

// Biquad DF2T, B=512 channels, T=48000, fp32 — exact affine chunked scan.
//   Pass 1: per (channel, chunk) recurrence from z=0 -> offset w[b][k]
//   Combine: z_start[k+1] = A^C z_start[k] + w[k]  (A^C via fp64 pow),
//            software-pipelined batches so L2 latency is hidden.
//   Pass 3: recurrence from z_start, write y. y stores use .cs (evict-first)
//           and x reads use .cs so pass 1's L2-resident copy of x survives
//           and pass 3's reads hit L2 instead of DRAM.
//
// All global traffic is coalesced float4. x tiles are register-pipelined
// (group g+1's LDGs issued before group g's FMA chain). Smem pad-33 tiles
// transpose between coalesced I/O layout and lane-owns-a-channel compute
// layout; all smem patterns are bank-conflict-free.

#define B_CH   512
#define T_LEN  48000
#define C_LEN  160          // chunk length
#define K_CHK  300          // T_LEN / C_LEN
#define NGR    5            // 32-sample groups per chunk
#define WPB    4            // warps per block
#define NGRP   16           // channel groups of 32
#define NBLK   ((NGRP * K_CHK) / WPB)   // 1200 blocks

__device__ float2 g_wz[K_CHK * B_CH];   // zero-state chunk-end state
__device__ float2 g_zs[K_CHK * B_CH];   // true chunk-start state

template <bool WRITE_Y>
__global__ __launch_bounds__(WPB * 32) void biquad_pass(
    const float* __restrict__ x,
    const float* __restrict__ b0p, const float* __restrict__ b1p,
    const float* __restrict__ b2p, const float* __restrict__ a1p,
    const float* __restrict__ a2p, float* __restrict__ out)
{
    __shared__ float tile[WPB][32][33];   // pad-33: conflict-free everywhere

    const int w    = threadIdx.x >> 5;
    const int lane = threadIdx.x & 31;
    const int wg   = blockIdx.x * WPB + w;      // 0 .. NGRP*K_CHK-1
    const int cg   = wg & (NGRP - 1);           // channel group
    const int k    = wg >> 4;                   // chunk index
    const int ch   = cg * 32 + lane;

    const float b0  = b0p[ch], b1 = b1p[ch], b2 = b2p[ch];
    const float na1 = -a1p[ch], na2 = -a2p[ch];

    float z1, z2;
    if (WRITE_Y) {
        const float2 zz = g_zs[k * B_CH + ch];
        z1 = zz.x; z2 = zz.y;
    } else {
        z1 = 0.0f; z2 = 0.0f;
    }

    const int lr  = lane >> 3;          // 0..3   (row within 4-row slab)
    const int lc  = (lane & 7) * 4;     // 0..28  (float4 column)
    const float* __restrict__ xbase = x + (size_t)(cg * 32) * T_LEN + k * C_LEN;
    float* __restrict__ obase = WRITE_Y
        ? out + (size_t)(cg * 32) * T_LEN + k * C_LEN : nullptr;

    auto ldx = [&](int g, int i) -> float4 {
        const float4* p = reinterpret_cast<const float4*>(
            xbase + (size_t)(i * 4 + lr) * T_LEN + g * 32 + lc);
        return WRITE_Y ? __ldcs(p) : *p;   // pass 3: last use, evict-first
    };

    // Prologue: coalesced load of group 0 into registers (4 lines / LDG).
    float4 r[8];
    #pragma unroll
    for (int i = 0; i < 8; i++) r[i] = ldx(0, i);

    #pragma unroll 1
    for (int g = 0; g < NGR; g++) {
        // Scatter register tile into smem (conflict-free per (i, d)).
        #pragma unroll
        for (int i = 0; i < 8; i++) {
            const int rr = i * 4 + lr;
            tile[w][rr][lc + 0] = r[i].x;
            tile[w][rr][lc + 1] = r[i].y;
            tile[w][rr][lc + 2] = r[i].z;
            tile[w][rr][lc + 3] = r[i].w;
        }
        __syncwarp();

        // Prefetch next group NOW — these LDGs ride out the FMA chain.
        if (g + 1 < NGR) {
            #pragma unroll
            for (int i = 0; i < 8; i++) r[i] = ldx(g + 1, i);
        }

        // Serial DF2T over this lane's channel row (bank = (lane+j) mod 32).
        #pragma unroll
        for (int j = 0; j < 32; j++) {
            const float xv = tile[w][lane][j];
            const float y  = fmaf(b0, xv, z1);
            const float t  = fmaf(b1, xv, z2);
            z1 = fmaf(na1, y, t);
            z2 = fmaf(na2, y, b2 * xv);
            if (WRITE_Y) tile[w][lane][j] = y;   // own row: no hazard
        }
        __syncwarp();

        if (WRITE_Y) {
            // Coalesced gather-store of the y tile, evict-first (.cs) so
            // y traffic does not displace x from L2.
            #pragma unroll
            for (int i = 0; i < 8; i++) {
                const int rr = i * 4 + lr;
                const float* src = &tile[w][rr][lc];
                float4 vv;
                vv.x = src[0]; vv.y = src[1]; vv.z = src[2]; vv.w = src[3];
                __stcs(reinterpret_cast<float4*>(
                    obase + (size_t)rr * T_LEN + g * 32 + lc), vv);
            }
            __syncwarp();
        }
    }

    if (!WRITE_Y) {
        g_wz[k * B_CH + ch] = make_float2(z1, z2);
    }
}

#define CB      15                 // combine batch size
#define NBATCH  (K_CHK / CB)       // 20 batches (even, required by pipeline)

__global__ void biquad_combine(const float* __restrict__ a1p,
                               const float* __restrict__ a2p)
{
    const int b = blockIdx.x * blockDim.x + threadIdx.x;
    if (b >= B_CH) return;

    const double a1 = (double)a1p[b];
    const double a2 = (double)a2p[b];

    // A = [[-a1, 1], [-a2, 0]]; A^C_LEN by repeated squaring in fp64.
    double r00 = 1.0, r01 = 0.0, r10 = 0.0, r11 = 1.0;
    double p00 = -a1, p01 = 1.0, p10 = -a2, p11 = 0.0;
    int e = C_LEN;
    while (e) {
        if (e & 1) {
            const double n00 = r00 * p00 + r01 * p10;
            const double n01 = r00 * p01 + r01 * p11;
            const double n10 = r10 * p00 + r11 * p10;
            const double n11 = r10 * p01 + r11 * p11;
            r00 = n00; r01 = n01; r10 = n10; r11 = n11;
        }
        e >>= 1;
        if (e) {
            const double q00 = p00 * p00 + p01 * p10;
            const double q01 = p00 * p01 + p01 * p11;
            const double q10 = p10 * p00 + p11 * p10;
            const double q11 = p10 * p01 + p11 * p11;
            p00 = q00; p01 = q01; p10 = q10; p11 = q11;
        }
    }
    const float m00 = (float)r00, m01 = (float)r01;
    const float m10 = (float)r10, m11 = (float)r11;

    float z1 = 0.0f, z2 = 0.0f;
    float2 wA[CB], wB[CB];

    auto loadb = [&](float2* buf, int t) {
        #pragma unroll
        for (int i = 0; i < CB; i++)
            buf[i] = g_wz[(t * CB + i) * B_CH + b];
    };
    auto procb = [&](const float2* buf, int t) {
        #pragma unroll
        for (int i = 0; i < CB; i++) {
            g_zs[(t * CB + i) * B_CH + b] = make_float2(z1, z2);
            const float n1 = fmaf(m00, z1, fmaf(m01, z2, buf[i].x));
            const float n2 = fmaf(m10, z1, fmaf(m11, z2, buf[i].y));
            z1 = n1; z2 = n2;
        }
    };

    // Software-pipelined: batch t+1's loads are in flight during batch t's
    // dependent FMA chain, hiding the L2 round-trip.
    loadb(wA, 0);
    #pragma unroll 1
    for (int t = 0; t < NBATCH; t += 2) {
        loadb(wB, t + 1);
        procb(wA, t);
        if (t + 2 < NBATCH) loadb(wA, t + 2);
        procb(wB, t + 1);
    }
}

extern "C" void kernel_launch(void* const* d_in, const int* in_sizes, int n_in,
                              void* d_out, int out_size)
{
    const float* x  = (const float*)d_in[0];
    const float* b0 = (const float*)d_in[1];
    const float* b1 = (const float*)d_in[2];
    const float* b2 = (const float*)d_in[3];
    const float* a1 = (const float*)d_in[4];
    const float* a2 = (const float*)d_in[5];
    float* out = (float*)d_out;

    biquad_pass<false><<<NBLK, WPB * 32>>>(x, b0, b1, b2, a1, a2, nullptr);
    biquad_combine<<<16, 32>>>(a1, a2);
    biquad_pass<true><<<NBLK, WPB * 32>>>(x, b0, b1, b2, a1, a2, out);
}